// round 16
// baseline (speedup 1.0000x reference)
#include <cuda_runtime.h>
#include <cuda_bf16.h>
#include <mma.h>
#include <cstdint>

using namespace nvcuda;

#define S_MAX 200000
#define N_MAX 250000
#define LB 64           // L == B == 64
#define KSPAN 512       // K-range per k_zt block
#define KSUB 64         // staged sub-slab

// ---- device scratch (no allocations allowed) ----
__device__ float g_xT[(size_t)N_MAX * LB];            // x transposed [N,64]
__device__ __nv_bfloat16 g_XH[(size_t)S_MAX * LB];    // xagg split hi [S,64]
__device__ __nv_bfloat16 g_XL[(size_t)S_MAX * LB];    // xagg split lo [S,64]
__device__ float g_yT[(size_t)S_MAX * LB];            // y transposed [S,64]
__device__ float g_z[LB * LB];                        // z stored l-major: z[l][b]
__device__ int   g_cm[S_MAX];
__device__ int   g_cnt[N_MAX];
__device__ float g_bdacc[N_MAX];
__device__ unsigned char g_added[N_MAX];
// CSR A: master m -> added new nodes n
__device__ int   g_offA[S_MAX];
__device__ int   g_fillA[S_MAX];
__device__ int   g_idxA[N_MAX];
// CSR Y: new node n -> masters m
__device__ int   g_offY[N_MAX];
__device__ int   g_fillY[N_MAX];
__device__ int   g_idxY[S_MAX];
// scan temporaries
__device__ int   g_bsumA[1024];
__device__ int   g_boffA[1024];
__device__ int   g_bsumB[1024];
__device__ int   g_boffB[1024];

__device__ __forceinline__ void bsplit(float v, __nv_bfloat16& h, __nv_bfloat16& l) {
    h = __float2bfloat16(v);
    l = __float2bfloat16(v - __bfloat162float(h));
}
// packed split-bf16 pair
__device__ __forceinline__ void bsplit2(float a, float b, uint32_t& h, uint32_t& l) {
    __nv_bfloat162 h2 = __floats2bfloat162_rn(a, b);
    float ra = a - __low2float(h2);
    float rb = b - __high2float(h2);
    __nv_bfloat162 l2 = __floats2bfloat162_rn(ra, rb);
    h = *(uint32_t*)&h2;
    l = *(uint32_t*)&l2;
}

// k_zt dyn smem: 2 buffers x { WeH, WeL, XH, XL } each 64x72 bf16 = 73728 B
#define ZT_SMEM 73728
// k_y1m dyn smem: AH/AL 64x136 bf16, BH/BL 64x72 bf16 = 53248 B
#define Y1_SMEM 53248

__global__ void k_zt(const float*, int);
__global__ void k_y1m(const float*, int);

// ---- streams/events (created pre-capture) ----
static cudaStream_t s2, s3;
static cudaEvent_t evRoot, evStats, evXT, evFY;
namespace {
struct InitStreams {
    InitStreams() {
        cudaStreamCreateWithFlags(&s2, cudaStreamNonBlocking);
        cudaStreamCreateWithFlags(&s3, cudaStreamNonBlocking);
        cudaEventCreateWithFlags(&evRoot, cudaEventDisableTiming);
        cudaEventCreateWithFlags(&evStats, cudaEventDisableTiming);
        cudaEventCreateWithFlags(&evXT, cudaEventDisableTiming);
        cudaEventCreateWithFlags(&evFY, cudaEventDisableTiming);
        cudaFuncSetAttribute(k_zt,  cudaFuncAttributeMaxDynamicSharedMemorySize, ZT_SMEM);
        cudaFuncSetAttribute(k_y1m, cudaFuncAttributeMaxDynamicSharedMemorySize, Y1_SMEM);
    }
} s_init;
}

// ---------------- prep ----------------
__global__ void k_prep(const float* __restrict__ be, int S, int N) {
    int i = blockIdx.x * blockDim.x + threadIdx.x;
    if (i < S) { g_cm[i] = 0; g_fillA[i] = 0; }
    if (i < N) { g_cnt[i] = 0; g_bdacc[i] = 0.f; g_fillY[i] = 0; }
    if (i < LB * LB) g_z[i] = be[i >> 6];
}

// ---------------- stats ----------------
__global__ void k_stats(const int* __restrict__ nn_n, const int* __restrict__ nn_m,
                        const float* __restrict__ bd, int S, int N) {
    int i = blockIdx.x * blockDim.x + threadIdx.x;
    if (i < N) {
        int m = nn_n[i];
        int a = (nn_m[m] != i) ? 1 : 0;
        g_added[i] = (unsigned char)a;
        if (a) atomicAdd(&g_cm[m], 1);
    }
    if (i < S) {
        int nm = nn_m[i];
        atomicAdd(&g_cnt[nm], 1);
        atomicAdd(&g_bdacc[nm], bd[i]);
    }
}

// ---------------- x transpose ----------------
__global__ void k_xT(const float* __restrict__ x, int N) {
    __shared__ float tile[32][33];
    int n0 = blockIdx.x * 32;
    int b0 = blockIdx.y * 32;
    int tx = threadIdx.x, ty = threadIdx.y;
    #pragma unroll
    for (int i = 0; i < 32; i += 8) {
        int n = n0 + tx;
        tile[ty + i][tx] = (n < N) ? x[(size_t)(b0 + ty + i) * N + n] : 0.f;
    }
    __syncthreads();
    #pragma unroll
    for (int i = 0; i < 32; i += 8) {
        int n = n0 + ty + i;
        if (n < N) g_xT[(size_t)n * LB + b0 + tx] = tile[tx][ty + i];
    }
}

// ---------------- scans (3-kernel chains) ----------------
__global__ void k_scan1A(int S) {
    __shared__ int sd[256];
    int t = threadIdx.x;
    int n = blockIdx.x * 256 + t;
    sd[t] = (n < S) ? g_cm[n] : 0;
    __syncthreads();
    #pragma unroll
    for (int d = 128; d > 0; d >>= 1) { if (t < d) sd[t] += sd[t + d]; __syncthreads(); }
    if (t == 0) g_bsumA[blockIdx.x] = sd[0];
}
__global__ void k_scan1B(int N) {
    __shared__ int sd[256];
    int t = threadIdx.x;
    int n = blockIdx.x * 256 + t;
    sd[t] = (n < N) ? g_cnt[n] : 0;
    __syncthreads();
    #pragma unroll
    for (int d = 128; d > 0; d >>= 1) { if (t < d) sd[t] += sd[t + d]; __syncthreads(); }
    if (t == 0) g_bsumB[blockIdx.x] = sd[0];
}
__global__ void k_scan2A(int nch) {
    __shared__ int sd[1024];
    int t = threadIdx.x;
    int v = (t < nch) ? g_bsumA[t] : 0;
    sd[t] = v;
    __syncthreads();
    #pragma unroll
    for (int d = 1; d < 1024; d <<= 1) {
        int add = (t >= d) ? sd[t - d] : 0;
        __syncthreads(); sd[t] += add; __syncthreads();
    }
    if (t < nch) g_boffA[t] = sd[t] - v;
}
__global__ void k_scan2B(int nch) {
    __shared__ int sd[1024];
    int t = threadIdx.x;
    int v = (t < nch) ? g_bsumB[t] : 0;
    sd[t] = v;
    __syncthreads();
    #pragma unroll
    for (int d = 1; d < 1024; d <<= 1) {
        int add = (t >= d) ? sd[t - d] : 0;
        __syncthreads(); sd[t] += add; __syncthreads();
    }
    if (t < nch) g_boffB[t] = sd[t] - v;
}
__global__ void k_scan3A(int S) {
    __shared__ int sd[256];
    int t = threadIdx.x;
    int n = blockIdx.x * 256 + t;
    int v = (n < S) ? g_cm[n] : 0;
    sd[t] = v;
    __syncthreads();
    #pragma unroll
    for (int d = 1; d < 256; d <<= 1) {
        int add = (t >= d) ? sd[t - d] : 0;
        __syncthreads(); sd[t] += add; __syncthreads();
    }
    if (n < S) g_offA[n] = g_boffA[blockIdx.x] + sd[t] - v;
}
__global__ void k_scan3B(int N) {
    __shared__ int sd[256];
    int t = threadIdx.x;
    int n = blockIdx.x * 256 + t;
    int v = (n < N) ? g_cnt[n] : 0;
    sd[t] = v;
    __syncthreads();
    #pragma unroll
    for (int d = 1; d < 256; d <<= 1) {
        int add = (t >= d) ? sd[t - d] : 0;
        __syncthreads(); sd[t] += add; __syncthreads();
    }
    if (n < N) g_offY[n] = g_boffB[blockIdx.x] + sd[t] - v;
}

// ---------------- CSR fills ----------------
__global__ void k_fillA(const int* __restrict__ nn_n, int N) {
    int i = blockIdx.x * blockDim.x + threadIdx.x;
    if (i < N && g_added[i]) {
        int m = nn_n[i];
        int pos = g_offA[m] + atomicAdd(&g_fillA[m], 1);
        g_idxA[pos] = i;
    }
}
__global__ void k_fillY(const int* __restrict__ nn_m, int S) {
    int i = blockIdx.x * blockDim.x + threadIdx.x;
    if (i < S) {
        int nm = nn_m[i];
        int pos = g_offY[nm] + atomicAdd(&g_fillY[nm], 1);
        g_idxY[pos] = i;
    }
}

// ---------------- Xagg: aggregate + scale + emit split-bf16 ----------------
__global__ void __launch_bounds__(256) k_xagg(const int* __restrict__ nn_m, int S) {
    int w = (blockIdx.x * blockDim.x + threadIdx.x) >> 5;
    int lane = threadIdx.x & 31;
    if (w >= S) return;
    int h = lane >> 4;
    int l16 = lane & 15;
    int cm = g_cm[w];
    float scale = 1.0f / (float)(cm + 1);
    float4 acc = make_float4(0.f, 0.f, 0.f, 0.f);
    if (h == 0)
        acc = *(const float4*)&g_xT[(size_t)nn_m[w] * 64 + l16 * 4];
    int o = g_offA[w];
    for (int s = h; s < cm; s += 2) {
        int n = g_idxA[o + s];
        float4 v = *(const float4*)&g_xT[(size_t)n * 64 + l16 * 4];
        acc.x += v.x; acc.y += v.y; acc.z += v.z; acc.w += v.w;
    }
    acc.x += __shfl_xor_sync(0xffffffffu, acc.x, 16);
    acc.y += __shfl_xor_sync(0xffffffffu, acc.y, 16);
    acc.z += __shfl_xor_sync(0xffffffffu, acc.z, 16);
    acc.w += __shfl_xor_sync(0xffffffffu, acc.w, 16);
    if (h == 0) {
        uint32_t h0, l0, h1, l1;
        bsplit2(acc.x * scale, acc.y * scale, h0, l0);
        bsplit2(acc.z * scale, acc.w * scale, h1, l1);
        size_t off = (size_t)w * 64 + l16 * 4;
        *(uint2*)&g_XH[off] = make_uint2(h0, h1);
        *(uint2*)&g_XL[off] = make_uint2(l0, l1);
    }
}

// ---------------- z GEMM via WMMA split-bf16 (streaming) ----------------
// We: converted on the fly. X: pure 16B copies from pre-split g_XH/g_XL.
__device__ __forceinline__ void zt_stage(__nv_bfloat16* buf, const float* __restrict__ We,
                                         int kbase, int S, int tid) {
    __nv_bfloat16* WeH = buf;
    __nv_bfloat16* WeL = buf + 4608;
    __nv_bfloat16* XH  = buf + 9216;
    __nv_bfloat16* XL  = buf + 13824;
    int r = tid >> 2;            // 0..63
    int c = (tid & 3) * 16;
    int k = kbase + r;
    bool val = (k < S);
    uint4 xh0 = {0,0,0,0}, xh1 = {0,0,0,0}, xl0 = {0,0,0,0}, xl1 = {0,0,0,0};
    if (val) {
        size_t off = (size_t)k * 64 + c;
        xh0 = *(const uint4*)&g_XH[off];  xh1 = *(const uint4*)&g_XH[off + 8];
        xl0 = *(const uint4*)&g_XL[off];  xl1 = *(const uint4*)&g_XL[off + 8];
    }
    int so = r * 72 + c;
    *(uint4*)&XH[so] = xh0;  *(uint4*)&XH[so + 8] = xh1;
    *(uint4*)&XL[so] = xl0;  *(uint4*)&XL[so + 8] = xl1;
    #pragma unroll
    for (int j = 0; j < 16; j += 4) {
        float4 w = val ? *(const float4*)&We[(size_t)k * 64 + c + j]
                       : make_float4(0.f, 0.f, 0.f, 0.f);
        float wv[4] = {w.x, w.y, w.z, w.w};
        #pragma unroll
        for (int u = 0; u < 4; u++) {
            __nv_bfloat16 hh, ll;
            bsplit(wv[u], hh, ll);
            WeH[so + j + u] = hh;
            WeL[so + j + u] = ll;
        }
    }
}

__global__ void __launch_bounds__(256) k_zt(const float* __restrict__ We, int S) {
    extern __shared__ char smraw[];
    __nv_bfloat16* smz = (__nv_bfloat16*)smraw;   // 2 buffers x 18432 elems
    int tid = threadIdx.x;
    int warp = tid >> 5;
    int k0 = blockIdx.x * KSPAN;

    wmma::fragment<wmma::accumulator, 16, 16, 16, float> acc[2];
    wmma::fill_fragment(acc[0], 0.f);
    wmma::fill_fragment(acc[1], 0.f);
    int lt = warp >> 1;              // l-tile 0..3
    int bt0 = (warp & 1) * 2;        // b-tiles bt0, bt0+1

    zt_stage(smz, We, k0, S, tid);
    __syncthreads();

    const int NSUB = KSPAN / KSUB;
    for (int s = 0; s < NSUB; s++) {
        if (s + 1 < NSUB)
            zt_stage(smz + ((s + 1) & 1) * 18432, We, k0 + (s + 1) * KSUB, S, tid);
        __nv_bfloat16* buf = smz + (s & 1) * 18432;
        __nv_bfloat16* WeH = buf;
        __nv_bfloat16* WeL = buf + 4608;
        __nv_bfloat16* XH  = buf + 9216;
        __nv_bfloat16* XL  = buf + 13824;
        #pragma unroll
        for (int kt = 0; kt < 4; kt++) {
            wmma::fragment<wmma::matrix_a, 16, 16, 16, __nv_bfloat16, wmma::col_major> aH, aL;
            wmma::load_matrix_sync(aH, WeH + kt * 16 * 72 + lt * 16, 72);
            wmma::load_matrix_sync(aL, WeL + kt * 16 * 72 + lt * 16, 72);
            #pragma unroll
            for (int q = 0; q < 2; q++) {
                int bt = bt0 + q;
                wmma::fragment<wmma::matrix_b, 16, 16, 16, __nv_bfloat16, wmma::row_major> bH, bL;
                wmma::load_matrix_sync(bH, XH + kt * 16 * 72 + bt * 16, 72);
                wmma::load_matrix_sync(bL, XL + kt * 16 * 72 + bt * 16, 72);
                wmma::mma_sync(acc[q], aH, bH, acc[q]);
                wmma::mma_sync(acc[q], aH, bL, acc[q]);
                wmma::mma_sync(acc[q], aL, bH, acc[q]);
            }
        }
        __syncthreads();
    }

    float* zz = (float*)smraw;
    wmma::store_matrix_sync(zz + (lt * 16) * 64 + bt0 * 16, acc[0], 64, wmma::mem_row_major);
    wmma::store_matrix_sync(zz + (lt * 16) * 64 + (bt0 + 1) * 16, acc[1], 64, wmma::mem_row_major);
    __syncthreads();
    int base = tid * 16;
    #pragma unroll
    for (int i = 0; i < 16; i++)
        atomicAdd(&g_z[base + i], zz[base + i]);
}

// ---------------- y = z @ Wd via WMMA split-bf16 (packed staging) ----------------
__global__ void __launch_bounds__(256) k_y1m(const float* __restrict__ Wd, int S) {
    extern __shared__ char smraw[];
    __nv_bfloat16* AH = (__nv_bfloat16*)smraw;        // 64*136
    __nv_bfloat16* AL = AH + 8704;
    __nv_bfloat16* BH = AH + 17408;                   // 64*72
    __nv_bfloat16* BL = AH + 22016;
    int tid = threadIdx.x;
    int m0 = blockIdx.x * 128;

    // stage z -> B hi/lo: packed cvt + uint32 stores
    for (int i = tid * 4; i < 4096; i += 1024) {
        float4 v = *(const float4*)&g_z[i];
        int l = i >> 6, b = i & 63;
        uint32_t h, lo;
        bsplit2(v.x, v.y, h, lo);
        *(uint32_t*)&BH[l * 72 + b]     = h;  *(uint32_t*)&BL[l * 72 + b]     = lo;
        bsplit2(v.z, v.w, h, lo);
        *(uint32_t*)&BH[l * 72 + b + 2] = h;  *(uint32_t*)&BL[l * 72 + b + 2] = lo;
    }
    // stage Wd -> A hi/lo: float2 loads (2 adjacent m), packed uint32 stores
    {
        int mm2 = (tid & 63) * 2;            // even m within tile
        int m = m0 + mm2;
        bool val = (m < S);                  // 2 | S: pair all-or-nothing
        for (int l = tid >> 6; l < 64; l += 4) {
            float2 w = val ? *(const float2*)&Wd[(size_t)l * S + m] : make_float2(0.f, 0.f);
            uint32_t h, lo;
            bsplit2(w.x, w.y, h, lo);
            *(uint32_t*)&AH[l * 136 + mm2] = h;
            *(uint32_t*)&AL[l * 136 + mm2] = lo;
        }
    }
    __syncthreads();

    int warp = tid >> 5;
    int mt16 = m0 + warp * 16;
    wmma::fragment<wmma::accumulator, 16, 16, 16, float> acc[4];
    #pragma unroll
    for (int q = 0; q < 4; q++) wmma::fill_fragment(acc[q], 0.f);

    #pragma unroll
    for (int kt = 0; kt < 4; kt++) {
        wmma::fragment<wmma::matrix_a, 16, 16, 16, __nv_bfloat16, wmma::col_major> aH, aL;
        wmma::load_matrix_sync(aH, AH + kt * 16 * 136 + warp * 16, 136);
        wmma::load_matrix_sync(aL, AL + kt * 16 * 136 + warp * 16, 136);
        #pragma unroll
        for (int bt = 0; bt < 4; bt++) {
            wmma::fragment<wmma::matrix_b, 16, 16, 16, __nv_bfloat16, wmma::row_major> bH, bL;
            wmma::load_matrix_sync(bH, BH + kt * 16 * 72 + bt * 16, 72);
            wmma::load_matrix_sync(bL, BL + kt * 16 * 72 + bt * 16, 72);
            wmma::mma_sync(acc[bt], aH, bH, acc[bt]);
            wmma::mma_sync(acc[bt], aH, bL, acc[bt]);
            wmma::mma_sync(acc[bt], aL, bH, acc[bt]);
        }
    }

    if (mt16 < S) {
        #pragma unroll
        for (int bt = 0; bt < 4; bt++)
            wmma::store_matrix_sync(&g_yT[(size_t)mt16 * 64 + bt * 16], acc[bt], 64,
                                    wmma::mem_row_major);
    }
}

// ---------------- finalize ----------------
__global__ void __launch_bounds__(256) k_y2(float* __restrict__ out,
                                            const float* __restrict__ bd,
                                            const int* __restrict__ nn_n, int N) {
    __shared__ float t[32][65];
    int n0 = blockIdx.x * 32;
    int tid = threadIdx.x;
    int r = tid >> 3;
    int q = (tid & 7) * 8;
    int n = n0 + r;
    if (n < N) {
        int a = g_added[n];
        int mstar = nn_n[n];
        int cnt = g_cnt[n];
        float dn = (float)(cnt + a);
        if (dn < 1.f) dn = 1.f;
        float inv = 1.0f / dn;
        float bdn = (g_bdacc[n] + (a ? bd[mstar] : 0.f)) * inv;

        float acc[8];
        #pragma unroll
        for (int j = 0; j < 8; j++) acc[j] = 0.f;

        int o = g_offY[n];
        for (int s = 0; s < cnt; s++) {
            int m = g_idxY[o + s];
            const float* yr = g_yT + (size_t)m * 64 + q;
            float4 v0 = *(const float4*)(yr);
            float4 v1 = *(const float4*)(yr + 4);
            acc[0] += v0.x; acc[1] += v0.y; acc[2] += v0.z; acc[3] += v0.w;
            acc[4] += v1.x; acc[5] += v1.y; acc[6] += v1.z; acc[7] += v1.w;
        }
        if (a) {
            const float* yr = g_yT + (size_t)mstar * 64 + q;
            float4 v0 = *(const float4*)(yr);
            float4 v1 = *(const float4*)(yr + 4);
            acc[0] += v0.x; acc[1] += v0.y; acc[2] += v0.z; acc[3] += v0.w;
            acc[4] += v1.x; acc[5] += v1.y; acc[6] += v1.z; acc[7] += v1.w;
        }
        #pragma unroll
        for (int j = 0; j < 8; j++) t[r][q + j] = acc[j] * inv + bdn;
    }
    __syncthreads();
    int cidx = tid & 31;
    if (n0 + cidx < N) {
        #pragma unroll
        for (int b = tid >> 5; b < 64; b += 8)
            out[(size_t)b * N + n0 + cidx] = t[cidx][b];
    }
}

extern "C" void kernel_launch(void* const* d_in, const int* in_sizes, int n_in,
                              void* d_out, int out_size) {
    const float* We   = (const float*)d_in[0];
    const float* be   = (const float*)d_in[1];
    const float* Wd   = (const float*)d_in[2];
    const float* bd   = (const float*)d_in[3];
    const float* x    = (const float*)d_in[4];
    const int*   nn_n = (const int*)d_in[5];
    const int*   nn_m = (const int*)d_in[6];
    int S = in_sizes[3];
    int N = in_sizes[5];
    float* out = (float*)d_out;

    int mx = (N > S) ? N : S;
    int cA = (S + 255) / 256;
    int cB = (N + 255) / 256;

    // fork: xT on s2 (depends only on x)
    cudaEventRecord(evRoot, 0);
    cudaStreamWaitEvent(s2, evRoot, 0);
    {
        dim3 tb(32, 8);
        dim3 tg((N + 31) / 32, 2);
        k_xT<<<tg, tb, 0, s2>>>(x, N);
    }
    cudaEventRecord(evXT, s2);

    // main chain
    k_prep<<<(mx + 255) / 256, 256>>>(be, S, N);
    k_stats<<<(mx + 255) / 256, 256>>>(nn_n, nn_m, bd, S, N);
    cudaEventRecord(evStats, 0);

    // side chain on s3: CSR-Y build (only needed by k_y2)
    cudaStreamWaitEvent(s3, evStats, 0);
    k_scan1B<<<cB, 256, 0, s3>>>(N);
    k_scan2B<<<1, 1024, 0, s3>>>(cB);
    k_scan3B<<<cB, 256, 0, s3>>>(N);
    k_fillY<<<(S + 255) / 256, 256, 0, s3>>>(nn_m, S);
    cudaEventRecord(evFY, s3);

    // main chain: CSR-A -> xagg -> zt -> y1m
    k_scan1A<<<cA, 256>>>(S);
    k_scan2A<<<1, 1024>>>(cA);
    k_scan3A<<<cA, 256>>>(S);
    k_fillA<<<(N + 255) / 256, 256>>>(nn_n, N);

    cudaStreamWaitEvent(0, evXT, 0);
    k_xagg<<<(S * 32 + 255) / 256, 256>>>(nn_m, S);
    k_zt<<<(S + KSPAN - 1) / KSPAN, 256, ZT_SMEM>>>(We, S);
    k_y1m<<<(S + 127) / 128, 256, Y1_SMEM>>>(Wd, S);

    // finalize
    cudaStreamWaitEvent(0, evFY, 0);
    k_y2<<<(N + 31) / 32, 256>>>(out, bd, nn_n, N);
}

// round 17
// speedup vs baseline: 1.0320x; 1.0320x over previous
#include <cuda_runtime.h>
#include <cuda_bf16.h>
#include <mma.h>
#include <cstdint>

using namespace nvcuda;

#define S_MAX 200000
#define N_MAX 250000
#define LB 64           // L == B == 64
#define KSPAN 512       // K-range per k_zt block
#define KSUB 64         // staged sub-slab

// ---- device scratch (no allocations allowed) ----
__device__ float g_xT[(size_t)N_MAX * LB];            // x transposed [N,64]
__device__ __nv_bfloat16 g_XH[(size_t)S_MAX * LB];    // xagg split hi [S,64]
__device__ __nv_bfloat16 g_XL[(size_t)S_MAX * LB];    // xagg split lo [S,64]
__device__ float g_yT[(size_t)S_MAX * LB];            // y transposed [S,64]
__device__ float g_z[LB * LB];                        // z stored l-major: z[l][b]
__device__ int   g_cm[S_MAX];
__device__ int   g_cnt[N_MAX];
__device__ float g_bdacc[N_MAX];
__device__ unsigned char g_added[N_MAX];
// CSR A: master m -> added new nodes n
__device__ int   g_offA[S_MAX];
__device__ int   g_fillA[S_MAX];
__device__ int   g_idxA[N_MAX];
// CSR Y: new node n -> masters m
__device__ int   g_offY[N_MAX];
__device__ int   g_fillY[N_MAX];
__device__ int   g_idxY[S_MAX];
// scan temporaries
__device__ int   g_bsumA[1024];
__device__ int   g_boffA[1024];
__device__ int   g_bsumB[1024];
__device__ int   g_boffB[1024];

__device__ __forceinline__ void bsplit(float v, __nv_bfloat16& h, __nv_bfloat16& l) {
    h = __float2bfloat16(v);
    l = __float2bfloat16(v - __bfloat162float(h));
}
// packed split-bf16 pair
__device__ __forceinline__ void bsplit2(float a, float b, uint32_t& h, uint32_t& l) {
    __nv_bfloat162 h2 = __floats2bfloat162_rn(a, b);
    float ra = a - __low2float(h2);
    float rb = b - __high2float(h2);
    __nv_bfloat162 l2 = __floats2bfloat162_rn(ra, rb);
    h = *(uint32_t*)&h2;
    l = *(uint32_t*)&l2;
}

// k_zt dyn smem: 2 buffers x { WeH, WeL, XH, XL } each 64x72 bf16 = 73728 B
#define ZT_SMEM 73728
// k_y1m dyn smem: AH/AL 64x136 bf16, BH/BL 64x72 bf16 = 53248 B
#define Y1_SMEM 53248

__global__ void k_zt(const float*, int);
__global__ void k_y1m(const float*, int);

// ---- streams/events (created pre-capture) ----
static cudaStream_t s2, s3;
static cudaEvent_t evRoot, evStats, evXT, evFY;
namespace {
struct InitStreams {
    InitStreams() {
        cudaStreamCreateWithFlags(&s2, cudaStreamNonBlocking);
        cudaStreamCreateWithFlags(&s3, cudaStreamNonBlocking);
        cudaEventCreateWithFlags(&evRoot, cudaEventDisableTiming);
        cudaEventCreateWithFlags(&evStats, cudaEventDisableTiming);
        cudaEventCreateWithFlags(&evXT, cudaEventDisableTiming);
        cudaEventCreateWithFlags(&evFY, cudaEventDisableTiming);
        cudaFuncSetAttribute(k_zt,  cudaFuncAttributeMaxDynamicSharedMemorySize, ZT_SMEM);
        cudaFuncSetAttribute(k_y1m, cudaFuncAttributeMaxDynamicSharedMemorySize, Y1_SMEM);
    }
} s_init;
}

// ---------------- prep ----------------
__global__ void k_prep(const float* __restrict__ be, int S, int N) {
    int i = blockIdx.x * blockDim.x + threadIdx.x;
    if (i < S) { g_cm[i] = 0; g_fillA[i] = 0; }
    if (i < N) { g_cnt[i] = 0; g_bdacc[i] = 0.f; g_fillY[i] = 0; }
    if (i < LB * LB) g_z[i] = be[i >> 6];
}

// ---------------- stats ----------------
__global__ void k_stats(const int* __restrict__ nn_n, const int* __restrict__ nn_m,
                        const float* __restrict__ bd, int S, int N) {
    int i = blockIdx.x * blockDim.x + threadIdx.x;
    if (i < N) {
        int m = nn_n[i];
        int a = (nn_m[m] != i) ? 1 : 0;
        g_added[i] = (unsigned char)a;
        if (a) atomicAdd(&g_cm[m], 1);
    }
    if (i < S) {
        int nm = nn_m[i];
        atomicAdd(&g_cnt[nm], 1);
        atomicAdd(&g_bdacc[nm], bd[i]);
    }
}

// ---------------- x transpose ----------------
__global__ void k_xT(const float* __restrict__ x, int N) {
    __shared__ float tile[32][33];
    int n0 = blockIdx.x * 32;
    int b0 = blockIdx.y * 32;
    int tx = threadIdx.x, ty = threadIdx.y;
    #pragma unroll
    for (int i = 0; i < 32; i += 8) {
        int n = n0 + tx;
        tile[ty + i][tx] = (n < N) ? x[(size_t)(b0 + ty + i) * N + n] : 0.f;
    }
    __syncthreads();
    #pragma unroll
    for (int i = 0; i < 32; i += 8) {
        int n = n0 + ty + i;
        if (n < N) g_xT[(size_t)n * LB + b0 + tx] = tile[tx][ty + i];
    }
}

// ---------------- scans (3-kernel chains) ----------------
__global__ void k_scan1A(int S) {
    __shared__ int sd[256];
    int t = threadIdx.x;
    int n = blockIdx.x * 256 + t;
    sd[t] = (n < S) ? g_cm[n] : 0;
    __syncthreads();
    #pragma unroll
    for (int d = 128; d > 0; d >>= 1) { if (t < d) sd[t] += sd[t + d]; __syncthreads(); }
    if (t == 0) g_bsumA[blockIdx.x] = sd[0];
}
__global__ void k_scan1B(int N) {
    __shared__ int sd[256];
    int t = threadIdx.x;
    int n = blockIdx.x * 256 + t;
    sd[t] = (n < N) ? g_cnt[n] : 0;
    __syncthreads();
    #pragma unroll
    for (int d = 128; d > 0; d >>= 1) { if (t < d) sd[t] += sd[t + d]; __syncthreads(); }
    if (t == 0) g_bsumB[blockIdx.x] = sd[0];
}
__global__ void k_scan2A(int nch) {
    __shared__ int sd[1024];
    int t = threadIdx.x;
    int v = (t < nch) ? g_bsumA[t] : 0;
    sd[t] = v;
    __syncthreads();
    #pragma unroll
    for (int d = 1; d < 1024; d <<= 1) {
        int add = (t >= d) ? sd[t - d] : 0;
        __syncthreads(); sd[t] += add; __syncthreads();
    }
    if (t < nch) g_boffA[t] = sd[t] - v;
}
__global__ void k_scan2B(int nch) {
    __shared__ int sd[1024];
    int t = threadIdx.x;
    int v = (t < nch) ? g_bsumB[t] : 0;
    sd[t] = v;
    __syncthreads();
    #pragma unroll
    for (int d = 1; d < 1024; d <<= 1) {
        int add = (t >= d) ? sd[t - d] : 0;
        __syncthreads(); sd[t] += add; __syncthreads();
    }
    if (t < nch) g_boffB[t] = sd[t] - v;
}
__global__ void k_scan3A(int S) {
    __shared__ int sd[256];
    int t = threadIdx.x;
    int n = blockIdx.x * 256 + t;
    int v = (n < S) ? g_cm[n] : 0;
    sd[t] = v;
    __syncthreads();
    #pragma unroll
    for (int d = 1; d < 256; d <<= 1) {
        int add = (t >= d) ? sd[t - d] : 0;
        __syncthreads(); sd[t] += add; __syncthreads();
    }
    if (n < S) g_offA[n] = g_boffA[blockIdx.x] + sd[t] - v;
}
__global__ void k_scan3B(int N) {
    __shared__ int sd[256];
    int t = threadIdx.x;
    int n = blockIdx.x * 256 + t;
    int v = (n < N) ? g_cnt[n] : 0;
    sd[t] = v;
    __syncthreads();
    #pragma unroll
    for (int d = 1; d < 256; d <<= 1) {
        int add = (t >= d) ? sd[t - d] : 0;
        __syncthreads(); sd[t] += add; __syncthreads();
    }
    if (n < N) g_offY[n] = g_boffB[blockIdx.x] + sd[t] - v;
}

// ---------------- CSR fills ----------------
__global__ void k_fillA(const int* __restrict__ nn_n, int N) {
    int i = blockIdx.x * blockDim.x + threadIdx.x;
    if (i < N && g_added[i]) {
        int m = nn_n[i];
        int pos = g_offA[m] + atomicAdd(&g_fillA[m], 1);
        g_idxA[pos] = i;
    }
}
__global__ void k_fillY(const int* __restrict__ nn_m, int S) {
    int i = blockIdx.x * blockDim.x + threadIdx.x;
    if (i < S) {
        int nm = nn_m[i];
        int pos = g_offY[nm] + atomicAdd(&g_fillY[nm], 1);
        g_idxY[pos] = i;
    }
}

// ---------------- Xagg: aggregate + scale + emit split-bf16 ----------------
__global__ void __launch_bounds__(256) k_xagg(const int* __restrict__ nn_m, int S) {
    int w = (blockIdx.x * blockDim.x + threadIdx.x) >> 5;
    int lane = threadIdx.x & 31;
    if (w >= S) return;
    int h = lane >> 4;
    int l16 = lane & 15;
    int cm = g_cm[w];
    float scale = 1.0f / (float)(cm + 1);
    float4 acc = make_float4(0.f, 0.f, 0.f, 0.f);
    if (h == 0)
        acc = *(const float4*)&g_xT[(size_t)nn_m[w] * 64 + l16 * 4];
    int o = g_offA[w];
    for (int s = h; s < cm; s += 2) {
        int n = g_idxA[o + s];
        float4 v = *(const float4*)&g_xT[(size_t)n * 64 + l16 * 4];
        acc.x += v.x; acc.y += v.y; acc.z += v.z; acc.w += v.w;
    }
    acc.x += __shfl_xor_sync(0xffffffffu, acc.x, 16);
    acc.y += __shfl_xor_sync(0xffffffffu, acc.y, 16);
    acc.z += __shfl_xor_sync(0xffffffffu, acc.z, 16);
    acc.w += __shfl_xor_sync(0xffffffffu, acc.w, 16);
    if (h == 0) {
        uint32_t h0, l0, h1, l1;
        bsplit2(acc.x * scale, acc.y * scale, h0, l0);
        bsplit2(acc.z * scale, acc.w * scale, h1, l1);
        size_t off = (size_t)w * 64 + l16 * 4;
        *(uint2*)&g_XH[off] = make_uint2(h0, h1);
        *(uint2*)&g_XL[off] = make_uint2(l0, l1);
    }
}

// ---------------- z GEMM via WMMA split-bf16 (streaming) ----------------
// We: converted on the fly. X: pure 16B copies from pre-split g_XH/g_XL.
__device__ __forceinline__ void zt_stage(__nv_bfloat16* buf, const float* __restrict__ We,
                                         int kbase, int S, int tid) {
    __nv_bfloat16* WeH = buf;
    __nv_bfloat16* WeL = buf + 4608;
    __nv_bfloat16* XH  = buf + 9216;
    __nv_bfloat16* XL  = buf + 13824;
    int r = tid >> 2;            // 0..63
    int c = (tid & 3) * 16;
    int k = kbase + r;
    bool val = (k < S);
    uint4 xh0 = {0,0,0,0}, xh1 = {0,0,0,0}, xl0 = {0,0,0,0}, xl1 = {0,0,0,0};
    if (val) {
        size_t off = (size_t)k * 64 + c;
        xh0 = *(const uint4*)&g_XH[off];  xh1 = *(const uint4*)&g_XH[off + 8];
        xl0 = *(const uint4*)&g_XL[off];  xl1 = *(const uint4*)&g_XL[off + 8];
    }
    int so = r * 72 + c;
    *(uint4*)&XH[so] = xh0;  *(uint4*)&XH[so + 8] = xh1;
    *(uint4*)&XL[so] = xl0;  *(uint4*)&XL[so + 8] = xl1;
    #pragma unroll
    for (int j = 0; j < 16; j += 4) {
        float4 w = val ? *(const float4*)&We[(size_t)k * 64 + c + j]
                       : make_float4(0.f, 0.f, 0.f, 0.f);
        float wv[4] = {w.x, w.y, w.z, w.w};
        #pragma unroll
        for (int u = 0; u < 4; u++) {
            __nv_bfloat16 hh, ll;
            bsplit(wv[u], hh, ll);
            WeH[so + j + u] = hh;
            WeL[so + j + u] = ll;
        }
    }
}

__global__ void __launch_bounds__(256) k_zt(const float* __restrict__ We, int S) {
    extern __shared__ char smraw[];
    __nv_bfloat16* smz = (__nv_bfloat16*)smraw;   // 2 buffers x 18432 elems
    int tid = threadIdx.x;
    int warp = tid >> 5;
    int k0 = blockIdx.x * KSPAN;

    wmma::fragment<wmma::accumulator, 16, 16, 16, float> acc[2];
    wmma::fill_fragment(acc[0], 0.f);
    wmma::fill_fragment(acc[1], 0.f);
    int lt = warp >> 1;              // l-tile 0..3
    int bt0 = (warp & 1) * 2;        // b-tiles bt0, bt0+1

    zt_stage(smz, We, k0, S, tid);
    __syncthreads();

    const int NSUB = KSPAN / KSUB;
    for (int s = 0; s < NSUB; s++) {
        if (s + 1 < NSUB)
            zt_stage(smz + ((s + 1) & 1) * 18432, We, k0 + (s + 1) * KSUB, S, tid);
        __nv_bfloat16* buf = smz + (s & 1) * 18432;
        __nv_bfloat16* WeH = buf;
        __nv_bfloat16* WeL = buf + 4608;
        __nv_bfloat16* XH  = buf + 9216;
        __nv_bfloat16* XL  = buf + 13824;
        #pragma unroll
        for (int kt = 0; kt < 4; kt++) {
            wmma::fragment<wmma::matrix_a, 16, 16, 16, __nv_bfloat16, wmma::col_major> aH, aL;
            wmma::load_matrix_sync(aH, WeH + kt * 16 * 72 + lt * 16, 72);
            wmma::load_matrix_sync(aL, WeL + kt * 16 * 72 + lt * 16, 72);
            #pragma unroll
            for (int q = 0; q < 2; q++) {
                int bt = bt0 + q;
                wmma::fragment<wmma::matrix_b, 16, 16, 16, __nv_bfloat16, wmma::row_major> bH, bL;
                wmma::load_matrix_sync(bH, XH + kt * 16 * 72 + bt * 16, 72);
                wmma::load_matrix_sync(bL, XL + kt * 16 * 72 + bt * 16, 72);
                wmma::mma_sync(acc[q], aH, bH, acc[q]);
                wmma::mma_sync(acc[q], aH, bL, acc[q]);
                wmma::mma_sync(acc[q], aL, bH, acc[q]);
            }
        }
        __syncthreads();
    }

    float* zz = (float*)smraw;
    wmma::store_matrix_sync(zz + (lt * 16) * 64 + bt0 * 16, acc[0], 64, wmma::mem_row_major);
    wmma::store_matrix_sync(zz + (lt * 16) * 64 + (bt0 + 1) * 16, acc[1], 64, wmma::mem_row_major);
    __syncthreads();
    int base = tid * 16;
    #pragma unroll
    for (int i = 0; i < 16; i++)
        atomicAdd(&g_z[base + i], zz[base + i]);
}

// ---------------- y = z @ Wd via WMMA split-bf16 (exact R15/R9 staging) ----------------
__global__ void __launch_bounds__(256) k_y1m(const float* __restrict__ Wd, int S) {
    extern __shared__ char smraw[];
    __nv_bfloat16* AH = (__nv_bfloat16*)smraw;        // 64*136
    __nv_bfloat16* AL = AH + 8704;
    __nv_bfloat16* BH = AH + 17408;                   // 64*72
    __nv_bfloat16* BL = AH + 22016;
    int tid = threadIdx.x;
    int m0 = blockIdx.x * 128;

    // stage z -> B hi/lo
    for (int i = tid * 4; i < 4096; i += 1024) {
        float4 v = *(const float4*)&g_z[i];
        int l = i >> 6, b = i & 63;
        float vv[4] = {v.x, v.y, v.z, v.w};
        #pragma unroll
        for (int u = 0; u < 4; u++) {
            __nv_bfloat16 h, lo;
            bsplit(vv[u], h, lo);
            BH[l * 72 + b + u] = h;
            BL[l * 72 + b + u] = lo;
        }
    }
    // stage Wd -> A hi/lo
    {
        int mm = tid & 127;
        int m = m0 + mm;
        bool val = (m < S);
        for (int l = tid >> 7; l < 64; l += 2) {
            float w = val ? Wd[(size_t)l * S + m] : 0.f;
            __nv_bfloat16 h, lo;
            bsplit(w, h, lo);
            AH[l * 136 + mm] = h;
            AL[l * 136 + mm] = lo;
        }
    }
    __syncthreads();

    int warp = tid >> 5;
    int mt16 = m0 + warp * 16;
    wmma::fragment<wmma::accumulator, 16, 16, 16, float> acc[4];
    #pragma unroll
    for (int q = 0; q < 4; q++) wmma::fill_fragment(acc[q], 0.f);

    #pragma unroll
    for (int kt = 0; kt < 4; kt++) {
        wmma::fragment<wmma::matrix_a, 16, 16, 16, __nv_bfloat16, wmma::col_major> aH, aL;
        wmma::load_matrix_sync(aH, AH + kt * 16 * 136 + warp * 16, 136);
        wmma::load_matrix_sync(aL, AL + kt * 16 * 136 + warp * 16, 136);
        #pragma unroll
        for (int bt = 0; bt < 4; bt++) {
            wmma::fragment<wmma::matrix_b, 16, 16, 16, __nv_bfloat16, wmma::row_major> bH, bL;
            wmma::load_matrix_sync(bH, BH + kt * 16 * 72 + bt * 16, 72);
            wmma::load_matrix_sync(bL, BL + kt * 16 * 72 + bt * 16, 72);
            wmma::mma_sync(acc[bt], aH, bH, acc[bt]);
            wmma::mma_sync(acc[bt], aH, bL, acc[bt]);
            wmma::mma_sync(acc[bt], aL, bH, acc[bt]);
        }
    }

    if (mt16 < S) {
        #pragma unroll
        for (int bt = 0; bt < 4; bt++)
            wmma::store_matrix_sync(&g_yT[(size_t)mt16 * 64 + bt * 16], acc[bt], 64,
                                    wmma::mem_row_major);
    }
}

// ---------------- finalize: 16 threads/n CSR gather ----------------
__global__ void __launch_bounds__(256) k_y2(float* __restrict__ out,
                                            const float* __restrict__ bd,
                                            const int* __restrict__ nn_n, int N) {
    __shared__ float t[16][65];
    int n0 = blockIdx.x * 16;
    int tid = threadIdx.x;
    int r = tid >> 4;               // n within tile 0..15
    int q = (tid & 15) * 4;         // 4 b-columns per thread
    int n = n0 + r;
    if (n < N) {
        int a = g_added[n];
        int mstar = nn_n[n];
        int cnt = g_cnt[n];
        float dn = (float)(cnt + a);
        if (dn < 1.f) dn = 1.f;
        float inv = 1.0f / dn;
        float bdn = (g_bdacc[n] + (a ? bd[mstar] : 0.f)) * inv;

        float4 acc = make_float4(0.f, 0.f, 0.f, 0.f);
        int o = g_offY[n];
        for (int s = 0; s < cnt; s++) {
            int m = g_idxY[o + s];
            float4 v = *(const float4*)(g_yT + (size_t)m * 64 + q);
            acc.x += v.x; acc.y += v.y; acc.z += v.z; acc.w += v.w;
        }
        if (a) {
            float4 v = *(const float4*)(g_yT + (size_t)mstar * 64 + q);
            acc.x += v.x; acc.y += v.y; acc.z += v.z; acc.w += v.w;
        }
        t[r][q]     = acc.x * inv + bdn;
        t[r][q + 1] = acc.y * inv + bdn;
        t[r][q + 2] = acc.z * inv + bdn;
        t[r][q + 3] = acc.w * inv + bdn;
    }
    __syncthreads();
    int cidx = tid & 15;
    if (n0 + cidx < N) {
        #pragma unroll
        for (int b = tid >> 4; b < 64; b += 16)
            out[(size_t)b * N + n0 + cidx] = t[cidx][b];
    }
}

extern "C" void kernel_launch(void* const* d_in, const int* in_sizes, int n_in,
                              void* d_out, int out_size) {
    const float* We   = (const float*)d_in[0];
    const float* be   = (const float*)d_in[1];
    const float* Wd   = (const float*)d_in[2];
    const float* bd   = (const float*)d_in[3];
    const float* x    = (const float*)d_in[4];
    const int*   nn_n = (const int*)d_in[5];
    const int*   nn_m = (const int*)d_in[6];
    int S = in_sizes[3];
    int N = in_sizes[5];
    float* out = (float*)d_out;

    int mx = (N > S) ? N : S;
    int cA = (S + 255) / 256;
    int cB = (N + 255) / 256;

    // fork: xT on s2 (depends only on x)
    cudaEventRecord(evRoot, 0);
    cudaStreamWaitEvent(s2, evRoot, 0);
    {
        dim3 tb(32, 8);
        dim3 tg((N + 31) / 32, 2);
        k_xT<<<tg, tb, 0, s2>>>(x, N);
    }
    cudaEventRecord(evXT, s2);

    // main chain
    k_prep<<<(mx + 255) / 256, 256>>>(be, S, N);
    k_stats<<<(mx + 255) / 256, 256>>>(nn_n, nn_m, bd, S, N);
    cudaEventRecord(evStats, 0);

    // side chain on s3: CSR-Y build (only needed by k_y2)
    cudaStreamWaitEvent(s3, evStats, 0);
    k_scan1B<<<cB, 256, 0, s3>>>(N);
    k_scan2B<<<1, 1024, 0, s3>>>(cB);
    k_scan3B<<<cB, 256, 0, s3>>>(N);
    k_fillY<<<(S + 255) / 256, 256, 0, s3>>>(nn_m, S);
    cudaEventRecord(evFY, s3);

    // main chain: CSR-A -> xagg -> zt -> y1m
    k_scan1A<<<cA, 256>>>(S);
    k_scan2A<<<1, 1024>>>(cA);
    k_scan3A<<<cA, 256>>>(S);
    k_fillA<<<(N + 255) / 256, 256>>>(nn_n, N);

    cudaStreamWaitEvent(0, evXT, 0);
    k_xagg<<<(S * 32 + 255) / 256, 256>>>(nn_m, S);
    k_zt<<<(S + KSPAN - 1) / KSPAN, 256, ZT_SMEM>>>(We, S);
    k_y1m<<<(S + 127) / 128, 256, Y1_SMEM>>>(Wd, S);

    // finalize
    cudaStreamWaitEvent(0, evFY, 0);
    k_y2<<<(N + 15) / 16, 256>>>(out, bd, nn_n, N);
}